// round 14
// baseline (speedup 1.0000x reference)
#include <cuda_runtime.h>
#include <cuda_bf16.h>
#include <math.h>
#include <stdint.h>

#define T_SEQ   512
#define GATES   500
#define HID     125
#define DHID    250      // 2*HID
#define MLPH    512
#define NN      512

// Scratch (device globals; no allocation allowed)
__device__ float g_A[2 * T_SEQ * GATES];   // input projections (fwd/bwd)
__device__ float g_H[T_SEQ * DHID];        // concat hidden states
__device__ float g_P[2 * NN * MLPH];       // Pa, Pb(+b1)

// ---------------------------------------------------------------------------
// helpers
// ---------------------------------------------------------------------------
typedef unsigned long long ull;

__device__ __forceinline__ ull ffma2u(ull a, ull b, ull c) {
    ull d;
    asm("fma.rn.f32x2 %0, %1, %2, %3;" : "=l"(d) : "l"(a), "l"(b), "l"(c));
    return d;
}
__device__ __forceinline__ ull fadd2u(ull a, ull b) {
    ull d;
    asm("add.rn.f32x2 %0, %1, %2;" : "=l"(d) : "l"(a), "l"(b));
    return d;
}
__device__ __forceinline__ float2 u2f2(ull v) {
    float2 r;
    asm("mov.b64 {%0, %1}, %2;" : "=f"(r.x), "=f"(r.y) : "l"(v));
    return r;
}
__device__ __forceinline__ float tanh_mufu(float x) {
    float y;
    asm("tanh.approx.f32 %0, %1;" : "=f"(y) : "f"(x));
    return y;
}
__device__ __forceinline__ unsigned int smem_u32(const void* p) {
    unsigned int a;
    asm("{ .reg .u64 t; cvta.to.shared.u64 t, %1; cvt.u32.u64 %0, t; }"
        : "=r"(a) : "l"(p));
    return a;
}
__device__ __forceinline__ unsigned int mapa_u32(unsigned int addr, unsigned int rank) {
    unsigned int r;
    asm("mapa.shared::cluster.u32 %0, %1, %2;" : "=r"(r) : "r"(addr), "r"(rank));
    return r;
}
__device__ __forceinline__ void st_async_b32(unsigned int raddr, float v, unsigned int rmbar) {
    asm volatile(
        "st.async.shared::cluster.mbarrier::complete_tx::bytes.b32 [%0], %1, [%2];"
        :: "r"(raddr), "r"(__float_as_uint(v)), "r"(rmbar) : "memory");
}
__device__ __forceinline__ void mbar_init(unsigned int mbar, unsigned int cnt) {
    asm volatile("mbarrier.init.shared.b64 [%0], %1;" :: "r"(mbar), "r"(cnt) : "memory");
}
__device__ __forceinline__ void mbar_arrive_expect_tx(unsigned int mbar, unsigned int tx) {
    asm volatile("mbarrier.arrive.expect_tx.shared.b64 _, [%0], %1;"
                 :: "r"(mbar), "r"(tx) : "memory");
}
__device__ __forceinline__ void mbar_wait_parity(unsigned int mbar, unsigned int parity) {
    asm volatile(
        "{\n\t.reg .pred P;\n\t"
        "WL_%=:\n\t"
        "mbarrier.try_wait.parity.acquire.cluster.shared::cta.b64 P, [%0], %1, 0x989680;\n\t"
        "@P bra.uni WD_%=;\n\t"
        "bra.uni WL_%=;\n\t"
        "WD_%=:\n\t}"
        :: "r"(mbar), "r"(parity) : "memory");
}
__device__ __forceinline__ void cluster_sync() {
    asm volatile("barrier.cluster.arrive.aligned;" ::: "memory");
    asm volatile("barrier.cluster.wait.aligned;" ::: "memory");
}

// no-op kernels to keep the ncu capture slot on lstm_kernel
__device__ int g_sink;
__global__ void nudge_kernel() {
    if (threadIdx.x > 4096) g_sink = 1;   // never taken
}

// ---------------------------------------------------------------------------
// Input projection, both directions in one launch.
// ---------------------------------------------------------------------------
__global__ void __launch_bounds__(256) proj_kernel(
    const float* __restrict__ x,
    const float* __restrict__ Wih_f, const float* __restrict__ bih_f,
    const float* __restrict__ bhh_f,
    const float* __restrict__ Wih_b, const float* __restrict__ bih_b,
    const float* __restrict__ bhh_b,
    float* __restrict__ Aout)
{
    const int dir = blockIdx.z;
    const float* __restrict__ W  = dir ? Wih_b : Wih_f;
    const float* __restrict__ bi = dir ? bih_b : bih_f;
    const float* __restrict__ bh = dir ? bhh_b : bhh_f;
    float* __restrict__ C = Aout + dir * (T_SEQ * GATES);

    __shared__ float As[16][34];
    __shared__ float Bs[16][34];

    const int tid = threadIdx.x;
    const int ti = tid & 15;
    const int tn = tid >> 4;
    const int m0 = blockIdx.x * 32;
    const int n0 = blockIdx.y * 32;

    float acc00 = 0.f, acc01 = 0.f, acc10 = 0.f, acc11 = 0.f;

    for (int kc = 0; kc < 125; kc += 16) {
#pragma unroll
        for (int it = 0; it < 2; ++it) {
            int idx = tid + it * 256;
            int mm = idx >> 4, kk = idx & 15;
            int k = kc + kk;
            int m = m0 + mm;
            int ra = dir ? (T_SEQ - 1 - m) : m;
            As[kk][mm] = (k < 125) ? x[(long)ra * 125 + k] : 0.f;
            int n = n0 + mm;
            Bs[kk][mm] = (n < GATES && k < 125) ? W[(long)n * 125 + k] : 0.f;
        }
        __syncthreads();
#pragma unroll
        for (int kk = 0; kk < 16; ++kk) {
            float2 av = *(const float2*)&As[kk][2 * ti];
            float2 bv = *(const float2*)&Bs[kk][2 * tn];
            acc00 = fmaf(av.x, bv.x, acc00);
            acc01 = fmaf(av.x, bv.y, acc01);
            acc10 = fmaf(av.y, bv.x, acc10);
            acc11 = fmaf(av.y, bv.y, acc11);
        }
        __syncthreads();
    }

    int m_ = m0 + 2 * ti;
    int n_ = n0 + 2 * tn;
    float b0 = 0.f, b1v = 0.f;
    if (n_ < GATES)     b0  = bi[n_] + bh[n_];
    if (n_ + 1 < GATES) b1v = bi[n_ + 1] + bh[n_ + 1];
    if (n_ < GATES) {
        C[(long)m_ * GATES + n_]       = acc00 + b0;
        C[(long)(m_ + 1) * GATES + n_] = acc10 + b0;
    }
    if (n_ + 1 < GATES) {
        C[(long)m_ * GATES + n_ + 1]       = acc01 + b1v;
        C[(long)(m_ + 1) * GATES + n_ + 1] = acc11 + b1v;
    }
}

// ---------------------------------------------------------------------------
// Pa / Pb in one launch. grid (16,16,2), block 256.
// ---------------------------------------------------------------------------
__global__ void __launch_bounds__(256) pab_kernel(
    const float* __restrict__ H,
    const float* __restrict__ W1,
    const float* __restrict__ b1,
    float* __restrict__ P)
{
    const int z = blockIdx.z;
    const float* __restrict__ B = W1 + (z ? DHID : 0);
    float* __restrict__ C = P + (long)z * NN * MLPH;

    __shared__ float As[16][34];
    __shared__ float Bs[16][34];

    const int tid = threadIdx.x;
    const int ti = tid & 15;
    const int tn = tid >> 4;
    const int m0 = blockIdx.x * 32;
    const int n0 = blockIdx.y * 32;

    float acc00 = 0.f, acc01 = 0.f, acc10 = 0.f, acc11 = 0.f;

    for (int kc = 0; kc < DHID; kc += 16) {
#pragma unroll
        for (int it = 0; it < 2; ++it) {
            int idx = tid + it * 256;
            int mm = idx >> 4, kk = idx & 15;
            int k = kc + kk;
            As[kk][mm] = (k < DHID) ? H[(long)(m0 + mm) * DHID + k] : 0.f;
            Bs[kk][mm] = (k < DHID) ? B[(long)(n0 + mm) * 500 + k] : 0.f;
        }
        __syncthreads();
#pragma unroll
        for (int kk = 0; kk < 16; ++kk) {
            float2 av = *(const float2*)&As[kk][2 * ti];
            float2 bv = *(const float2*)&Bs[kk][2 * tn];
            acc00 = fmaf(av.x, bv.x, acc00);
            acc01 = fmaf(av.x, bv.y, acc01);
            acc10 = fmaf(av.y, bv.x, acc10);
            acc11 = fmaf(av.y, bv.y, acc11);
        }
        __syncthreads();
    }

    int m_ = m0 + 2 * ti;
    int n_ = n0 + 2 * tn;
    float b0 = 0.f, b1v = 0.f;
    if (z) { b0 = b1[n_]; b1v = b1[n_ + 1]; }
    C[(long)m_ * MLPH + n_]           = acc00 + b0;
    C[(long)m_ * MLPH + n_ + 1]       = acc01 + b1v;
    C[(long)(m_ + 1) * MLPH + n_]     = acc10 + b0;
    C[(long)(m_ + 1) * MLPH + n_ + 1] = acc11 + b1v;
}

// ---------------------------------------------------------------------------
// LSTM recurrence, 4-CTA cluster per direction, split by gate.
// Same as R13 except: gbuf laid out [unit][gate] so the combine is one
// LDS.128; matvec uses 4 accumulator chains (8-deep) to halve exposed
// FMA latency.
// ---------------------------------------------------------------------------
#define TXB (4u * 128u * 4u)   // bytes per target mbarrier per step

__global__ void __cluster_dims__(4, 1, 1) __launch_bounds__(256, 1) lstm_kernel(
    const float* __restrict__ Whh_f,
    const float* __restrict__ Whh_b,
    const float* __restrict__ A,     // [2][512][500]
    float* __restrict__ H)           // [512][250]
{
    __shared__ __align__(16) float sh_h[2][128];    // double-buffered h
    __shared__ __align__(16) float gbuf[2][512];    // [phase][unit*4 + gate]
    __shared__ __align__(8)  ull   mbar[2];

    const int tid = threadIdx.x;
    const int g   = blockIdx.x & 3;          // cluster rank = gate (i,f,g,o)
    const int dir = blockIdx.x >> 2;
    const float* __restrict__ Whh = dir ? Whh_b : Whh_f;
    const float* __restrict__ Ad = A + dir * (T_SEQ * GATES);

    const int lane = tid & 31;
    const int w    = tid >> 5;
    const int hi   = lane >> 4;               // column half 0/1
    const int u    = (w << 4) | (lane & 15);  // unit 0..127 (125..127 pad)
    const bool st_ok = (u < HID);
    int r = g * 125 + u;
    if (r > 499) r = 499;                     // clamp pad rows (bounded values)

    // activation: g-gate (rank 2) -> tanh ; others -> sigmoid
    const float m_act  = (g == 2) ? 1.0f : 0.5f;
    const float a0_act = (g == 2) ? 0.0f : 0.5f;

    // register weights: 32 packed pairs = cols 64*hi .. 64*hi+63 (>=125 -> 0)
    ull wreg[32];
    {
        const float* wf = Whh + r * 125;
#pragma unroll
        for (int p = 0; p < 32; ++p) {
            int c0 = 64 * hi + 2 * p;
            float v0 = (c0 < 125)     ? wf[c0]     : 0.f;
            float v1 = (c0 + 1 < 125) ? wf[c0 + 1] : 0.f;
            float2 t = make_float2(v0, v1);
            wreg[p] = *(ull*)&t;
        }
    }

    // init smem / barriers
    ((float*)sh_h)[tid] = 0.f;                // zero both h buffers
    const unsigned int mb0 = smem_u32(&mbar[0]);
    const unsigned int mb1 = smem_u32(&mbar[1]);
    if (tid == 0) {
        mbar_init(mb0, 1);
        mbar_init(mb1, 1);
        mbar_arrive_expect_tx(mb0, TXB);      // arm step 0
        mbar_arrive_expect_tx(mb1, TXB);      // arm step 1
    }
    float creg = 0.f;
    float a_cur = Ad[r];
    __syncthreads();
    cluster_sync();                            // barriers visible cluster-wide

    // precomputed remote addresses: hi half stores to ranks {2hi, 2hi+1}
    const unsigned int rk0 = 2 * hi, rk1 = 2 * hi + 1;
    const unsigned int la0 = smem_u32(&gbuf[0][4 * u + g]);
    const unsigned int la1 = smem_u32(&gbuf[1][4 * u + g]);
    const unsigned int d00 = mapa_u32(la0, rk0), d01 = mapa_u32(la0, rk1);
    const unsigned int d10 = mapa_u32(la1, rk0), d11 = mapa_u32(la1, rk1);
    const unsigned int m00 = mapa_u32(mb0, rk0),  m01 = mapa_u32(mb0, rk1);
    const unsigned int m10 = mapa_u32(mb1, rk0),  m11 = mapa_u32(mb1, rk1);

    for (int t = 0; t < T_SEQ; ++t) {
        const int b = t & 1;
        const bool has_next = (t < T_SEQ - 1);
        float a_next = has_next ? Ad[(t + 1) * GATES + r] : 0.f;

        // matvec: 16 h-granules (cols 64*hi ..), 4 accumulator chains
        const ulonglong2* h2 = (const ulonglong2*)sh_h[b];
        ull a0 = 0ull, a1 = 0ull, a2 = 0ull, a3 = 0ull;
#pragma unroll
        for (int p = 0; p < 8; ++p) {
            ulonglong2 hv = h2[16 * hi + p];
            a0 = ffma2u(wreg[2 * p],     hv.x, a0);
            a1 = ffma2u(wreg[2 * p + 1], hv.y, a1);
        }
#pragma unroll
        for (int p = 8; p < 16; ++p) {
            ulonglong2 hv = h2[16 * hi + p];
            a2 = ffma2u(wreg[2 * p],     hv.x, a2);
            a3 = ffma2u(wreg[2 * p + 1], hv.y, a3);
        }
        float2 fs = u2f2(fadd2u(fadd2u(a0, a1), fadd2u(a2, a3)));
        float part = fs.x + fs.y;
        float s = part + __shfl_xor_sync(0xffffffffu, part, 16) + a_cur;
        float act = fmaf(m_act, tanh_mufu(m_act * s), a0_act);

        // broadcast activated gate value to my two target ranks
        if (b == 0) {
            st_async_b32(d00, act, m00);
            st_async_b32(d01, act, m01);
        } else {
            st_async_b32(d10, act, m10);
            st_async_b32(d11, act, m11);
        }

        // wait for all 4 gates from all CTAs
        mbar_wait_parity(b ? mb1 : mb0, (t >> 1) & 1);
        if (tid == 0)
            mbar_arrive_expect_tx(b ? mb1 : mb0, TXB);   // arm step t+2

        // combine (redundant on every CTA) — one LDS.128
        float4 gv4 = *(const float4*)&gbuf[b][4 * u];
        creg = gv4.y * creg + gv4.x * gv4.z;   // c = f*c + i*g
        float hv = gv4.w * tanh_mufu(creg);    // h = o*tanh(c)
        if (hi == 0 && st_ok) {
            sh_h[b ^ 1][u] = hv;
            if (g == 0) {
                int row = dir ? (T_SEQ - 1 - t) : t;
                H[row * DHID + dir * HID + u] = hv;
            }
        }
        __syncthreads();
        a_cur = a_next;
    }
    cluster_sync();
}

// ---------------------------------------------------------------------------
// Pairwise MLP contraction:
//   out[j][i] = b2 + sum_k W2[k] * tanh(Pa[i][k] + Pb[j][k])
// Tile 16(i) x 32(j), grid (32,16) = 512 CTAs for wave balance.
// Thread t: ti = t&7 (i pair), tj = t>>3 (j). 1x2 outputs per thread.
// ---------------------------------------------------------------------------
__global__ void __launch_bounds__(256) pair_kernel(
    const float* __restrict__ Pa,   // [512][512]
    const float* __restrict__ Pb,   // [512][512] (b1 folded in)
    const float* __restrict__ W2,   // [512]
    const float* __restrict__ b2,   // [1]
    float* __restrict__ out)        // [512][512]  row=j, col=i
{
    __shared__ float pas[64][18];
    __shared__ float pbs[64][34];
    __shared__ float w2s[64];

    const int tid = threadIdx.x;
    const int ti = tid & 7;      // i pair (0..7)
    const int tj = tid >> 3;     // j (0..31)
    const int i0 = blockIdx.x * 16;
    const int j0 = blockIdx.y * 32;

    float acc0 = 0.f, acc1 = 0.f;

    for (int kc = 0; kc < MLPH; kc += 64) {
        {   // stage Pa rows (16 x 64): one float4 per thread
            int row = tid >> 4, q = tid & 15;
            float4 va = *(const float4*)&Pa[(long)(i0 + row) * MLPH + kc + 4 * q];
            pas[4 * q + 0][row] = va.x; pas[4 * q + 1][row] = va.y;
            pas[4 * q + 2][row] = va.z; pas[4 * q + 3][row] = va.w;
        }
#pragma unroll
        for (int it = 0; it < 2; ++it) {   // stage Pb rows (32 x 64)
            int idx = tid + it * 256;
            int row = idx >> 4, q = idx & 15;
            float4 vb = *(const float4*)&Pb[(long)(j0 + row) * MLPH + kc + 4 * q];
            pbs[4 * q + 0][row] = vb.x; pbs[4 * q + 1][row] = vb.y;
            pbs[4 * q + 2][row] = vb.z; pbs[4 * q + 3][row] = vb.w;
        }
        if (tid < 16) {
            float4 wv = *(const float4*)&W2[kc + 4 * tid];
            w2s[4 * tid + 0] = wv.x; w2s[4 * tid + 1] = wv.y;
            w2s[4 * tid + 2] = wv.z; w2s[4 * tid + 3] = wv.w;
        }
        __syncthreads();
#pragma unroll
        for (int kk = 0; kk < 64; ++kk) {
            float wv = w2s[kk];
            float2 a = *(const float2*)&pas[kk][2 * ti];
            float bv = pbs[kk][tj];
            acc0 = fmaf(wv, tanh_mufu(a.x + bv), acc0);
            acc1 = fmaf(wv, tanh_mufu(a.y + bv), acc1);
        }
        __syncthreads();
    }

    float bb = b2[0];
    int i = i0 + 2 * ti;
    int j = j0 + tj;
    *(float2*)&out[(long)j * NN + i] = make_float2(acc0 + bb, acc1 + bb);
}

// ---------------------------------------------------------------------------
// launch
// ---------------------------------------------------------------------------
extern "C" void kernel_launch(void* const* d_in, const int* in_sizes, int n_in,
                              void* d_out, int out_size)
{
    const float* x     = (const float*)d_in[0];   // (512,1,125)
    const float* Wih_f = (const float*)d_in[1];
    const float* Whh_f = (const float*)d_in[2];
    const float* bih_f = (const float*)d_in[3];
    const float* bhh_f = (const float*)d_in[4];
    const float* Wih_b = (const float*)d_in[5];
    const float* Whh_b = (const float*)d_in[6];
    const float* bih_b = (const float*)d_in[7];
    const float* bhh_b = (const float*)d_in[8];
    const float* W1    = (const float*)d_in[9];   // (512,500)
    const float* b1    = (const float*)d_in[10];  // (512)
    const float* W2    = (const float*)d_in[11];  // (1,512)
    const float* b2    = (const float*)d_in[12];  // (1)
    float* out = (float*)d_out;

    float *pA, *pH, *pP;
    cudaGetSymbolAddress((void**)&pA, g_A);
    cudaGetSymbolAddress((void**)&pH, g_H);
    cudaGetSymbolAddress((void**)&pP, g_P);
    float* pPa = pP;
    float* pPb = pP + NN * MLPH;

    dim3 blk(256);
    // keep launch-slot layout so ncu's captured launch stays on lstm_kernel
    nudge_kernel<<<1, 32>>>();
    nudge_kernel<<<1, 32>>>();
    proj_kernel<<<dim3(16, 16, 2), blk>>>(x, Wih_f, bih_f, bhh_f,
                                          Wih_b, bih_b, bhh_b, pA);
    lstm_kernel<<<8, 256>>>(Whh_f, Whh_b, pA, pH);
    pab_kernel<<<dim3(16, 16, 2), blk>>>(pH, W1, b1, pP);
    pair_kernel<<<dim3(32, 16), blk>>>(pPa, pPb, W2, b2, out);
}

// round 15
// speedup vs baseline: 1.8081x; 1.8081x over previous
#include <cuda_runtime.h>
#include <cuda_bf16.h>
#include <math.h>
#include <stdint.h>

#define T_SEQ   512
#define GATES   500
#define HID     125
#define DHID    250      // 2*HID
#define MLPH    512
#define NN      512

// Scratch (device globals; no allocation allowed)
__device__ float g_A[2 * T_SEQ * GATES];   // input projections (fwd/bwd)
__device__ float g_H[T_SEQ * DHID];        // concat hidden states
__device__ float g_P[2 * NN * MLPH];       // Pa, Pb(+b1)

// ---------------------------------------------------------------------------
// helpers
// ---------------------------------------------------------------------------
typedef unsigned long long ull;

__device__ __forceinline__ ull ffma2u(ull a, ull b, ull c) {
    ull d;
    asm("fma.rn.f32x2 %0, %1, %2, %3;" : "=l"(d) : "l"(a), "l"(b), "l"(c));
    return d;
}
__device__ __forceinline__ ull fadd2u(ull a, ull b) {
    ull d;
    asm("add.rn.f32x2 %0, %1, %2;" : "=l"(d) : "l"(a), "l"(b));
    return d;
}
__device__ __forceinline__ float2 u2f2(ull v) {
    float2 r;
    asm("mov.b64 {%0, %1}, %2;" : "=f"(r.x), "=f"(r.y) : "l"(v));
    return r;
}
__device__ __forceinline__ float tanh_mufu(float x) {
    float y;
    asm("tanh.approx.f32 %0, %1;" : "=f"(y) : "f"(x));
    return y;
}
__device__ __forceinline__ unsigned int smem_u32(const void* p) {
    unsigned int a;
    asm("{ .reg .u64 t; cvta.to.shared.u64 t, %1; cvt.u32.u64 %0, t; }"
        : "=r"(a) : "l"(p));
    return a;
}
__device__ __forceinline__ unsigned int mapa_u32(unsigned int addr, unsigned int rank) {
    unsigned int r;
    asm("mapa.shared::cluster.u32 %0, %1, %2;" : "=r"(r) : "r"(addr), "r"(rank));
    return r;
}
__device__ __forceinline__ void st_async_b32(unsigned int raddr, float v, unsigned int rmbar) {
    asm volatile(
        "st.async.shared::cluster.mbarrier::complete_tx::bytes.b32 [%0], %1, [%2];"
        :: "r"(raddr), "r"(__float_as_uint(v)), "r"(rmbar) : "memory");
}
__device__ __forceinline__ void mbar_init(unsigned int mbar, unsigned int cnt) {
    asm volatile("mbarrier.init.shared.b64 [%0], %1;" :: "r"(mbar), "r"(cnt) : "memory");
}
__device__ __forceinline__ void mbar_arrive_expect_tx(unsigned int mbar, unsigned int tx) {
    asm volatile("mbarrier.arrive.expect_tx.shared.b64 _, [%0], %1;"
                 :: "r"(mbar), "r"(tx) : "memory");
}
__device__ __forceinline__ void mbar_wait_parity(unsigned int mbar, unsigned int parity) {
    asm volatile(
        "{\n\t.reg .pred P;\n\t"
        "WL_%=:\n\t"
        "mbarrier.try_wait.parity.acquire.cluster.shared::cta.b64 P, [%0], %1, 0x989680;\n\t"
        "@P bra.uni WD_%=;\n\t"
        "bra.uni WL_%=;\n\t"
        "WD_%=:\n\t}"
        :: "r"(mbar), "r"(parity) : "memory");
}
__device__ __forceinline__ void cluster_sync() {
    asm volatile("barrier.cluster.arrive.aligned;" ::: "memory");
    asm volatile("barrier.cluster.wait.aligned;" ::: "memory");
}

// no-op kernels to keep the ncu capture slot on lstm_kernel
__device__ int g_sink;
__global__ void nudge_kernel() {
    if (threadIdx.x > 4096) g_sink = 1;   // never taken
}

// ---------------------------------------------------------------------------
// Input projection, both directions in one launch.
// ---------------------------------------------------------------------------
__global__ void __launch_bounds__(256) proj_kernel(
    const float* __restrict__ x,
    const float* __restrict__ Wih_f, const float* __restrict__ bih_f,
    const float* __restrict__ bhh_f,
    const float* __restrict__ Wih_b, const float* __restrict__ bih_b,
    const float* __restrict__ bhh_b,
    float* __restrict__ Aout)
{
    const int dir = blockIdx.z;
    const float* __restrict__ W  = dir ? Wih_b : Wih_f;
    const float* __restrict__ bi = dir ? bih_b : bih_f;
    const float* __restrict__ bh = dir ? bhh_b : bhh_f;
    float* __restrict__ C = Aout + dir * (T_SEQ * GATES);

    __shared__ float As[16][34];
    __shared__ float Bs[16][34];

    const int tid = threadIdx.x;
    const int ti = tid & 15;
    const int tn = tid >> 4;
    const int m0 = blockIdx.x * 32;
    const int n0 = blockIdx.y * 32;

    float acc00 = 0.f, acc01 = 0.f, acc10 = 0.f, acc11 = 0.f;

    for (int kc = 0; kc < 125; kc += 16) {
#pragma unroll
        for (int it = 0; it < 2; ++it) {
            int idx = tid + it * 256;
            int mm = idx >> 4, kk = idx & 15;
            int k = kc + kk;
            int m = m0 + mm;
            int ra = dir ? (T_SEQ - 1 - m) : m;
            As[kk][mm] = (k < 125) ? x[(long)ra * 125 + k] : 0.f;
            int n = n0 + mm;
            Bs[kk][mm] = (n < GATES && k < 125) ? W[(long)n * 125 + k] : 0.f;
        }
        __syncthreads();
#pragma unroll
        for (int kk = 0; kk < 16; ++kk) {
            float2 av = *(const float2*)&As[kk][2 * ti];
            float2 bv = *(const float2*)&Bs[kk][2 * tn];
            acc00 = fmaf(av.x, bv.x, acc00);
            acc01 = fmaf(av.x, bv.y, acc01);
            acc10 = fmaf(av.y, bv.x, acc10);
            acc11 = fmaf(av.y, bv.y, acc11);
        }
        __syncthreads();
    }

    int m_ = m0 + 2 * ti;
    int n_ = n0 + 2 * tn;
    float b0 = 0.f, b1v = 0.f;
    if (n_ < GATES)     b0  = bi[n_] + bh[n_];
    if (n_ + 1 < GATES) b1v = bi[n_ + 1] + bh[n_ + 1];
    if (n_ < GATES) {
        C[(long)m_ * GATES + n_]       = acc00 + b0;
        C[(long)(m_ + 1) * GATES + n_] = acc10 + b0;
    }
    if (n_ + 1 < GATES) {
        C[(long)m_ * GATES + n_ + 1]       = acc01 + b1v;
        C[(long)(m_ + 1) * GATES + n_ + 1] = acc11 + b1v;
    }
}

// ---------------------------------------------------------------------------
// Pa / Pb in one launch. grid (16,16,2), block 256.
// ---------------------------------------------------------------------------
__global__ void __launch_bounds__(256) pab_kernel(
    const float* __restrict__ H,
    const float* __restrict__ W1,
    const float* __restrict__ b1,
    float* __restrict__ P)
{
    const int z = blockIdx.z;
    const float* __restrict__ B = W1 + (z ? DHID : 0);
    float* __restrict__ C = P + (long)z * NN * MLPH;

    __shared__ float As[16][34];
    __shared__ float Bs[16][34];

    const int tid = threadIdx.x;
    const int ti = tid & 15;
    const int tn = tid >> 4;
    const int m0 = blockIdx.x * 32;
    const int n0 = blockIdx.y * 32;

    float acc00 = 0.f, acc01 = 0.f, acc10 = 0.f, acc11 = 0.f;

    for (int kc = 0; kc < DHID; kc += 16) {
#pragma unroll
        for (int it = 0; it < 2; ++it) {
            int idx = tid + it * 256;
            int mm = idx >> 4, kk = idx & 15;
            int k = kc + kk;
            As[kk][mm] = (k < DHID) ? H[(long)(m0 + mm) * DHID + k] : 0.f;
            Bs[kk][mm] = (k < DHID) ? B[(long)(n0 + mm) * 500 + k] : 0.f;
        }
        __syncthreads();
#pragma unroll
        for (int kk = 0; kk < 16; ++kk) {
            float2 av = *(const float2*)&As[kk][2 * ti];
            float2 bv = *(const float2*)&Bs[kk][2 * tn];
            acc00 = fmaf(av.x, bv.x, acc00);
            acc01 = fmaf(av.x, bv.y, acc01);
            acc10 = fmaf(av.y, bv.x, acc10);
            acc11 = fmaf(av.y, bv.y, acc11);
        }
        __syncthreads();
    }

    int m_ = m0 + 2 * ti;
    int n_ = n0 + 2 * tn;
    float b0 = 0.f, b1v = 0.f;
    if (z) { b0 = b1[n_]; b1v = b1[n_ + 1]; }
    C[(long)m_ * MLPH + n_]           = acc00 + b0;
    C[(long)m_ * MLPH + n_ + 1]       = acc01 + b1v;
    C[(long)(m_ + 1) * MLPH + n_]     = acc10 + b0;
    C[(long)(m_ + 1) * MLPH + n_ + 1] = acc11 + b1v;
}

// ---------------------------------------------------------------------------
// LSTM recurrence, 4-CTA cluster per direction, split by UNIT (not gate).
// grid = 8, cluster = 4. dir = blockIdx.x >> 2; rank owns units [32r, 32r+32).
// Block 256: local row rl = 16w + (lane&15) in 0..127 = gate gg (rl>>5) x
// local unit v (rl&31); hi = lane>>4 = column half. Thread computes global
// gate row gg*125 + (rank*32+v) over cols [64hi, 64hi+64), weights fp32 in
// registers. c and h are computed LOCALLY by 32 owner threads (rl<32, hi=0);
// only h (32 floats) is broadcast via st.async to all 4 ranks (incl. self) —
// DSMEM payload 512B/step vs 2048B for the gate-split version.
// Double-buffered sh_h + 2 mbarriers, parity (t>>1)&1; wait at loop top.
// ---------------------------------------------------------------------------
#define TXB (4u * 32u * 4u)   // 512 bytes: 32 h-values from each of 4 ranks

__global__ void __cluster_dims__(4, 1, 1) __launch_bounds__(256, 1) lstm_kernel(
    const float* __restrict__ Whh_f,
    const float* __restrict__ Whh_b,
    const float* __restrict__ A,     // [2][512][500]
    float* __restrict__ H)           // [512][250]
{
    __shared__ __align__(16) float sh_h[2][128];    // double-buffered h
    __shared__ __align__(16) float sact[128];       // activated gates (local)
    __shared__ __align__(8)  ull   mbar[2];

    const int tid  = threadIdx.x;
    const int rank = blockIdx.x & 3;
    const int dir  = blockIdx.x >> 2;
    const float* __restrict__ Whh = dir ? Whh_b : Whh_f;
    const float* __restrict__ Ad = A + dir * (T_SEQ * GATES);

    const int lane = tid & 31;
    const int w    = tid >> 5;
    const int hi   = lane >> 4;                 // column half 0/1
    const int rl   = (w << 4) | (lane & 15);    // local row 0..127
    const int gg   = rl >> 5;                   // gate (i,f,g,o)
    const int v    = rl & 31;                   // local unit
    const int uu   = rank * 32 + v;             // global unit (>=125 pad)
    const int uuc  = (uu < HID) ? uu : (HID - 1);
    const int row  = gg * 125 + uuc;            // global gate row

    // activation: g-gate -> tanh ; others -> sigmoid
    const float m_act  = (gg == 2) ? 1.0f : 0.5f;
    const float a0_act = (gg == 2) ? 0.0f : 0.5f;

    // register weights: 32 packed pairs = cols 64*hi .. 64*hi+63 (>=125 -> 0)
    ull wreg[32];
    {
        const float* wf = Whh + row * 125;
#pragma unroll
        for (int p = 0; p < 32; ++p) {
            int c0 = 64 * hi + 2 * p;
            float v0 = (c0 < 125)     ? wf[c0]     : 0.f;
            float v1 = (c0 + 1 < 125) ? wf[c0 + 1] : 0.f;
            float2 t = make_float2(v0, v1);
            wreg[p] = *(ull*)&t;
        }
    }

    // init smem / barriers
    ((float*)sh_h)[tid] = 0.f;                // zero both h buffers
    const unsigned int mb0 = smem_u32(&mbar[0]);
    const unsigned int mb1 = smem_u32(&mbar[1]);
    if (tid == 0) {
        mbar_init(mb0, 1);
        mbar_init(mb1, 1);
        mbar_arrive_expect_tx(mb0, TXB);      // arm for t=0
        mbar_arrive_expect_tx(mb1, TXB);      // arm for t=1
    }
    float creg = 0.f;
    float a_cur = Ad[row];
    __syncthreads();
    cluster_sync();                            // barriers visible cluster-wide

    // owners: rl < 32 (gg==0) and hi==0 -> 32 threads, unit vo = rl
    const bool owner = (rl < 32) && (hi == 0);
    const int  vo = rl & 31;
    const int  uo = rank * 32 + vo;           // global unit owned
    unsigned int d0[4], d1[4], m0[4], m1[4];
    {
        unsigned int la0 = smem_u32(&sh_h[0][uo < 128 ? uo : 127]);
        unsigned int la1 = smem_u32(&sh_h[1][uo < 128 ? uo : 127]);
#pragma unroll
        for (int j = 0; j < 4; ++j) {
            d0[j] = mapa_u32(la0, j);
            d1[j] = mapa_u32(la1, j);
            m0[j] = mapa_u32(mb0, j);
            m1[j] = mapa_u32(mb1, j);
        }
    }

    // pre-send zeros into sh_h[0] everywhere so mbar[0] flips for t=0
    if (owner) {
#pragma unroll
        for (int j = 0; j < 4; ++j) st_async_b32(d0[j], 0.f, m0[j]);
    }

    for (int t = 0; t < T_SEQ; ++t) {
        const int b = t & 1;
        const unsigned int mb = b ? mb1 : mb0;

        mbar_wait_parity(mb, (t >> 1) & 1);     // h(t) fully delivered
        if (tid == 0)
            mbar_arrive_expect_tx(mb, TXB);     // rearm for t+2

        const bool has_next = (t < T_SEQ - 1);
        float a_next = has_next ? Ad[(t + 1) * GATES + row] : 0.f;

        // matvec over sh_h[b]: 16 h-granules, 2 accumulator chains
        const ulonglong2* h2 = (const ulonglong2*)sh_h[b];
        ull acc0 = 0ull, acc1 = 0ull;
#pragma unroll
        for (int p = 0; p < 16; ++p) {
            ulonglong2 hv = h2[16 * hi + p];
            acc0 = ffma2u(wreg[2 * p],     hv.x, acc0);
            acc1 = ffma2u(wreg[2 * p + 1], hv.y, acc1);
        }
        float2 fs = u2f2(fadd2u(acc0, acc1));
        float part = fs.x + fs.y;
        float s = part + __shfl_xor_sync(0xffffffffu, part, 16) + a_cur;
        float act = fmaf(m_act, tanh_mufu(m_act * s), a0_act);

        if (hi == 0) sact[rl] = act;
        __syncthreads();

        if (owner) {
            float iv = sact[vo];
            float fv = sact[32 + vo];
            float gv = sact[64 + vo];
            float ov = sact[96 + vo];
            creg = fv * creg + iv * gv;
            float hv = ov * tanh_mufu(creg);
            if (b == 0) {
#pragma unroll
                for (int j = 0; j < 4; ++j) st_async_b32(d1[j], hv, m1[j]);
            } else {
#pragma unroll
                for (int j = 0; j < 4; ++j) st_async_b32(d0[j], hv, m0[j]);
            }
            if (uo < HID) {
                int row_t = dir ? (T_SEQ - 1 - t) : t;
                H[row_t * DHID + dir * HID + uo] = hv;
            }
        }
        a_cur = a_next;
    }
    cluster_sync();
}

// ---------------------------------------------------------------------------
// Pairwise MLP contraction (R13-proven version):
//   out[j][i] = b2 + sum_k W2[k] * tanh(Pa[i][k] + Pb[j][k])
// ---------------------------------------------------------------------------
__global__ void __launch_bounds__(256) pair_kernel(
    const float* __restrict__ Pa,   // [512][512]
    const float* __restrict__ Pb,   // [512][512] (b1 folded in)
    const float* __restrict__ W2,   // [512]
    const float* __restrict__ b2,   // [1]
    float* __restrict__ out)        // [512][512]  row=j, col=i
{
    __shared__ float pas[64][34];
    __shared__ float pbs[64][34];
    __shared__ float w2s[64];

    const int tid = threadIdx.x;
    const int ti = tid & 15;     // i pair
    const int tj = tid >> 4;     // j pair
    const int i0 = blockIdx.x * 32;
    const int j0 = blockIdx.y * 32;

    float acc00 = 0.f, acc01 = 0.f, acc10 = 0.f, acc11 = 0.f;

    for (int kc = 0; kc < MLPH; kc += 64) {
#pragma unroll
        for (int it = 0; it < 2; ++it) {
            int idx = tid + it * 256;
            int row = idx >> 4, q = idx & 15;
            float4 va = *(const float4*)&Pa[(long)(i0 + row) * MLPH + kc + 4 * q];
            pas[4 * q + 0][row] = va.x; pas[4 * q + 1][row] = va.y;
            pas[4 * q + 2][row] = va.z; pas[4 * q + 3][row] = va.w;
            float4 vb = *(const float4*)&Pb[(long)(j0 + row) * MLPH + kc + 4 * q];
            pbs[4 * q + 0][row] = vb.x; pbs[4 * q + 1][row] = vb.y;
            pbs[4 * q + 2][row] = vb.z; pbs[4 * q + 3][row] = vb.w;
        }
        if (tid < 16) {
            float4 wv = *(const float4*)&W2[kc + 4 * tid];
            w2s[4 * tid + 0] = wv.x; w2s[4 * tid + 1] = wv.y;
            w2s[4 * tid + 2] = wv.z; w2s[4 * tid + 3] = wv.w;
        }
        __syncthreads();
#pragma unroll
        for (int kk = 0; kk < 64; ++kk) {
            float wv = w2s[kk];
            float2 a = *(const float2*)&pas[kk][2 * ti];
            float2 b = *(const float2*)&pbs[kk][2 * tj];
            acc00 = fmaf(wv, tanh_mufu(a.x + b.x), acc00);
            acc01 = fmaf(wv, tanh_mufu(a.x + b.y), acc01);
            acc10 = fmaf(wv, tanh_mufu(a.y + b.x), acc10);
            acc11 = fmaf(wv, tanh_mufu(a.y + b.y), acc11);
        }
        __syncthreads();
    }

    float bb = b2[0];
    int i = i0 + 2 * ti;
    int j = j0 + 2 * tj;
    *(float2*)&out[(long)j * NN + i]       = make_float2(acc00 + bb, acc10 + bb);
    *(float2*)&out[(long)(j + 1) * NN + i] = make_float2(acc01 + bb, acc11 + bb);
}

// ---------------------------------------------------------------------------
// launch
// ---------------------------------------------------------------------------
extern "C" void kernel_launch(void* const* d_in, const int* in_sizes, int n_in,
                              void* d_out, int out_size)
{
    const float* x     = (const float*)d_in[0];   // (512,1,125)
    const float* Wih_f = (const float*)d_in[1];
    const float* Whh_f = (const float*)d_in[2];
    const float* bih_f = (const float*)d_in[3];
    const float* bhh_f = (const float*)d_in[4];
    const float* Wih_b = (const float*)d_in[5];
    const float* Whh_b = (const float*)d_in[6];
    const float* bih_b = (const float*)d_in[7];
    const float* bhh_b = (const float*)d_in[8];
    const float* W1    = (const float*)d_in[9];   // (512,500)
    const float* b1    = (const float*)d_in[10];  // (512)
    const float* W2    = (const float*)d_in[11];  // (1,512)
    const float* b2    = (const float*)d_in[12];  // (1)
    float* out = (float*)d_out;

    float *pA, *pH, *pP;
    cudaGetSymbolAddress((void**)&pA, g_A);
    cudaGetSymbolAddress((void**)&pH, g_H);
    cudaGetSymbolAddress((void**)&pP, g_P);
    float* pPa = pP;
    float* pPb = pP + NN * MLPH;

    dim3 blk(256);
    // keep launch-slot layout so ncu's captured launch stays on lstm_kernel
    nudge_kernel<<<1, 32>>>();
    nudge_kernel<<<1, 32>>>();
    proj_kernel<<<dim3(16, 16, 2), blk>>>(x, Wih_f, bih_f, bhh_f,
                                          Wih_b, bih_b, bhh_b, pA);
    lstm_kernel<<<8, 256>>>(Whh_f, Whh_b, pA, pH);
    pab_kernel<<<dim3(16, 16, 2), blk>>>(pH, W1, b1, pP);
    pair_kernel<<<dim3(16, 16), blk>>>(pPa, pPb, W2, b2, out);
}